// round 5
// baseline (speedup 1.0000x reference)
#include <cuda_runtime.h>

#define BATCH  32768
#define NCONT  56
#define NB     16
#define NCAT   8
#define NUNIQ  100
#define NCOMP  8
#define R      16            // rows per block
#define FS     8             // feature slots (threads per row)
#define FPT    7             // cont features per slot (56/8)
#define TPB    (R*FS)        // 128
#define BPITCH 225           // float4 pitch per staged B row (224 + 1 pad)
#define SEPF   1e-3f
#define T1F    10.0f

// Stable softplus via fast intrinsics (err << 1e-3 budget).
__device__ __forceinline__ float sp(float x) {
    float e = __expf(-fabsf(x));
    return fmaxf(x, 0.0f) + __logf(1.0f + e);
}

// smem layout (floats):
//  sB    : R * BPITCH * 4      = 14400   (staged B rows; reused for partials)
//  sW    : NB*NCONT*NCOMP      = 7168    (Wh in pass1, Wv in pass2)
//  sWic  : NB*NCONT            = 896
//  scodes: R*NCAT ints         = 128
#define SB_F   (R * BPITCH * 4)
#define SW_F   (NB * NCONT * NCOMP)
#define SWIC_F (NB * NCONT)
#define SMEM_F (SB_F + SW_F + SWIC_F + R * NCAT)

extern __shared__ float smem[];

__global__ void __launch_bounds__(TPB, 2) k_main(
    const float* __restrict__ B,
    const float* __restrict__ Bcat,
    const float* __restrict__ Wh,  const float* __restrict__ bh,
    const float* __restrict__ Wv,  const float* __restrict__ bv,
    const float* __restrict__ Wic, const float* __restrict__ bic,
    const float* __restrict__ Whc, const float* __restrict__ Wvc,
    const float* __restrict__ Wicc,
    float* __restrict__ out)
{
    float* sB   = smem;
    float* sW   = smem + SB_F;
    float* sWic = smem + SB_F + SW_F;
    int*   scodes = (int*)(smem + SB_F + SW_F + SWIC_F);

    const int tid = threadIdx.x;
    const int row0 = blockIdx.x * R;

    // ---- Stage B: 16 rows x 224 float4, fully coalesced ----
    {
        const float4* gB = reinterpret_cast<const float4*>(B) + (size_t)row0 * 224;
        float4* sB4 = reinterpret_cast<float4*>(sB);
        #pragma unroll
        for (int j = 0; j < 28; j++) {
            int idx = tid + j * TPB;            // 0..3583
            int r = idx / 224, c = idx - r * 224;
            sB4[r * BPITCH + c] = __ldg(gB + idx);
        }
    }
    // ---- Stage Wh (1792 float4) and Wic (224 float4), coalesced ----
    {
        const float4* g = reinterpret_cast<const float4*>(Wh);
        float4* s = reinterpret_cast<float4*>(sW);
        #pragma unroll
        for (int j = 0; j < 14; j++) s[tid + j * TPB] = __ldg(g + tid + j * TPB);
        const float4* gi = reinterpret_cast<const float4*>(Wic);
        float4* si = reinterpret_cast<float4*>(sWic);
        if (tid < 112) { si[tid] = __ldg(gi + tid); si[tid + 112] = __ldg(gi + tid + 112); }
    }
    // ---- Fused one-hot scan: 16 rows x 200 float4, coalesced ----
    {
        const float4* gC = reinterpret_cast<const float4*>(Bcat) + (size_t)row0 * 200;
        #pragma unroll
        for (int j = 0; j < 25; j++) {
            int idx = tid + j * TPB;            // 0..3199
            float4 v = __ldg(gC + idx);
            if (v.x > 0.5f || v.y > 0.5f || v.z > 0.5f || v.w > 0.5f) {
                float vals[4] = {v.x, v.y, v.z, v.w};
                #pragma unroll
                for (int q = 0; q < 4; q++) {
                    if (vals[q] > 0.5f) {
                        int e = idx * 4 + q;
                        int r = e / 800, ee = e - r * 800;
                        scodes[r * NCAT + ee / 100] = ee % 100;
                    }
                }
            }
        }
    }
    __syncthreads();

    const int fs  = tid >> 4;          // 0..7  (warp = 2 slots x 16 rows)
    const int r   = tid & 15;
    const int row = row0 + r;
    const float* bbase = sB + r * (BPITCH * 4);

    float hs[NCOMP], vs[NCOMP];
    #pragma unroll
    for (int c = 0; c < NCOMP; c++) { hs[c] = 0.0f; vs[c] = 0.0f; }
    float ic = 0.0f;

    const int code = scodes[r * NCAT + fs];     // my one cat feature

    // ================= PASS 1: H (+ IC continuous) =================
    for (int ii = 0; ii < FPT; ii++) {
        const int f = fs * FPT + ii;
        const float4* bp = reinterpret_cast<const float4*>(bbase) + f * 4;
        float4 b0 = bp[0], b1 = bp[1], b2 = bp[2], b3 = bp[3];
        float bvv[NB] = {b0.x,b0.y,b0.z,b0.w, b1.x,b1.y,b1.z,b1.w,
                         b2.x,b2.y,b2.z,b2.w, b3.x,b3.y,b3.z,b3.w};
        float h[NCOMP];
        #pragma unroll
        for (int c = 0; c < NCOMP; c++) h[c] = 0.0f;
        #pragma unroll
        for (int k = 0; k < NB; k++) {
            const float4* w = reinterpret_cast<const float4*>(sW + (k * NCONT + f) * NCOMP);
            float4 w0 = w[0], w1 = w[1];
            const float bk = bvv[k];
            h[0] = fmaf(bk, w0.x, h[0]); h[1] = fmaf(bk, w0.y, h[1]);
            h[2] = fmaf(bk, w0.z, h[2]); h[3] = fmaf(bk, w0.w, h[3]);
            h[4] = fmaf(bk, w1.x, h[4]); h[5] = fmaf(bk, w1.y, h[5]);
            h[6] = fmaf(bk, w1.z, h[6]); h[7] = fmaf(bk, w1.w, h[7]);
            ic   = fmaf(bk, sWic[k * NCONT + f], ic);
        }
        #pragma unroll
        for (int c = 0; c < NCOMP; c++) hs[c] += sp(h[c]);
    }
    // cat: H + IC gathers (L1/L2-resident tables)
    {
        const float4* wh = reinterpret_cast<const float4*>(Whc + (fs * NUNIQ + code) * NCOMP);
        float4 a0 = __ldg(wh + 0), a1 = __ldg(wh + 1);
        hs[0] += sp(a0.x); hs[1] += sp(a0.y); hs[2] += sp(a0.z); hs[3] += sp(a0.w);
        hs[4] += sp(a1.x); hs[5] += sp(a1.y); hs[6] += sp(a1.z); hs[7] += sp(a1.w);
        ic += __ldg(Wicc + fs * NUNIQ + code);
    }

    // ================= restage Wv over Wh =================
    __syncthreads();
    {
        const float4* g = reinterpret_cast<const float4*>(Wv);
        float4* s = reinterpret_cast<float4*>(sW);
        #pragma unroll
        for (int j = 0; j < 14; j++) s[tid + j * TPB] = __ldg(g + tid + j * TPB);
    }
    __syncthreads();

    // ================= PASS 2: V =================
    for (int ii = 0; ii < FPT; ii++) {
        const int f = fs * FPT + ii;
        const float4* bp = reinterpret_cast<const float4*>(bbase) + f * 4;
        float4 b0 = bp[0], b1 = bp[1], b2 = bp[2], b3 = bp[3];
        float bvv[NB] = {b0.x,b0.y,b0.z,b0.w, b1.x,b1.y,b1.z,b1.w,
                         b2.x,b2.y,b2.z,b2.w, b3.x,b3.y,b3.z,b3.w};
        float v[NCOMP];
        #pragma unroll
        for (int c = 0; c < NCOMP; c++) v[c] = 0.0f;
        #pragma unroll
        for (int k = 0; k < NB; k++) {
            const float4* w = reinterpret_cast<const float4*>(sW + (k * NCONT + f) * NCOMP);
            float4 w0 = w[0], w1 = w[1];
            const float bk = bvv[k];
            v[0] = fmaf(bk, w0.x, v[0]); v[1] = fmaf(bk, w0.y, v[1]);
            v[2] = fmaf(bk, w0.z, v[2]); v[3] = fmaf(bk, w0.w, v[3]);
            v[4] = fmaf(bk, w1.x, v[4]); v[5] = fmaf(bk, w1.y, v[5]);
            v[6] = fmaf(bk, w1.z, v[6]); v[7] = fmaf(bk, w1.w, v[7]);
        }
        #pragma unroll
        for (int c = 0; c < NCOMP; c++) vs[c] += sp(v[c]);
    }
    {
        const float4* wv = reinterpret_cast<const float4*>(Wvc + (fs * NUNIQ + code) * NCOMP);
        float4 c0 = __ldg(wv + 0), c1 = __ldg(wv + 1);
        vs[0] += sp(c0.x); vs[1] += sp(c0.y); vs[2] += sp(c0.z); vs[3] += sp(c0.w);
        vs[4] += sp(c1.x); vs[5] += sp(c1.y); vs[6] += sp(c1.z); vs[7] += sp(c1.w);
    }

    // ================= reduce over fslots + epilogue =================
    __syncthreads();                      // all smem reads done; reuse sB
    float* part = sB;                     // [tid][18]
    {
        float* p = part + tid * 18;
        #pragma unroll
        for (int c = 0; c < NCOMP; c++) { p[c] = hs[c]; p[NCOMP + c] = vs[c]; }
        p[16] = ic;
    }
    __syncthreads();

    if (tid < R) {
        float H[NCOMP], V[NCOMP], IC = 0.0f;
        #pragma unroll
        for (int c = 0; c < NCOMP; c++) { H[c] = 0.0f; V[c] = 0.0f; }
        #pragma unroll
        for (int f2 = 0; f2 < FS; f2++) {
            const float* p = part + (f2 * R + tid) * 18;
            #pragma unroll
            for (int c = 0; c < NCOMP; c++) { H[c] += p[c]; V[c] += p[NCOMP + c]; }
            IC += p[16];
        }
        // bias column
        #pragma unroll
        for (int c = 0; c < NCOMP; c++) {
            H[c] += sp(__ldg(bh + c));
            V[c] += sp(__ldg(bv + c));
        }
        IC += __ldg(bic);

        float2 o[NCOMP + 1];
        o[0] = make_float2(0.0f, IC);
        float cum = 0.0f, xc = IC;
        #pragma unroll
        for (int c = 0; c < NCOMP; c++) {
            cum += H[c];
            xc  += (c & 1) ? -V[c] : V[c];
            o[c + 1] = make_float2(cum + SEPF * (float)(c + 1), xc);
        }
        o[NCOMP].x = fmaxf(o[NCOMP - 1].x + SEPF, T1F);

        float2* op = reinterpret_cast<float2*>(out + (size_t)(row0 + tid) * 2 * (NCOMP + 1));
        #pragma unroll
        for (int j = 0; j < NCOMP + 1; j++) op[j] = o[j];
    }
}

extern "C" void kernel_launch(void* const* d_in, const int* in_sizes, int n_in,
                              void* d_out, int out_size)
{
    const float* B    = (const float*)d_in[0];
    const float* Bcat = (const float*)d_in[1];
    const float* Wh   = (const float*)d_in[2];
    const float* Whc  = (const float*)d_in[3];
    const float* bh   = (const float*)d_in[4];
    const float* Wv   = (const float*)d_in[5];
    const float* Wvc  = (const float*)d_in[6];
    const float* bv   = (const float*)d_in[7];
    const float* Wic  = (const float*)d_in[8];
    const float* Wicc = (const float*)d_in[9];
    const float* bic  = (const float*)d_in[10];
    float* out = (float*)d_out;

    const size_t smem = SMEM_F * sizeof(float);   // 90,368 B
    cudaFuncSetAttribute(k_main, cudaFuncAttributeMaxDynamicSharedMemorySize, (int)smem);

    k_main<<<BATCH / R, TPB, smem>>>(B, Bcat, Wh, bh, Wv, bv, Wic, bic,
                                     Whc, Wvc, Wicc, out);
}

// round 6
// speedup vs baseline: 2.2981x; 2.2981x over previous
#include <cuda_runtime.h>

#define BATCH  32768
#define NCONT  56
#define NB     16
#define NCAT   8
#define NUNIQ  100
#define NCOMP  8
#define TPB    256
#define WARPS  8            // per block
#define RPW    8            // rows per warp
#define RPB    64           // rows per block (8 warps x 8 rows)
#define NCHUNK 14           // 56 features / 4 per chunk
#define FPC    4            // features per chunk
#define FPITCH 20           // staged floats per feature (16 data + 4 pad)
#define RPITCH 80           // staged floats per row (4 * 20) ; 80 mod 32 = 16 -> conflict-free
#define BUF_F  (RPW * RPITCH)   // 640 floats per warp buffer
#define SEPF   1e-3f
#define T1F    10.0f

// smem float offsets
#define SWH    0
#define SWV    (NB * NCONT * NCOMP)            // 7168
#define SWIC   (2 * NB * NCONT * NCOMP)        // 14336
#define SBUF   (SWIC + NB * NCONT)             // 15232
#define SCODE  (SBUF + WARPS * BUF_F)          // 20352 (ints live here)
#define SMEM_F (SCODE + WARPS * RPW * NCAT)    // 20864 floats = 83456 B

// Stable softplus via fast intrinsics (err << 1e-3 budget; verified 5.8e-8 rel).
__device__ __forceinline__ float sp(float x) {
    float e = __expf(-fabsf(x));
    return fmaxf(x, 0.0f) + __logf(1.0f + e);
}

extern __shared__ float smem[];

__global__ void __launch_bounds__(TPB, 2) k_main(
    const float* __restrict__ B,
    const float* __restrict__ Bcat,
    const float* __restrict__ Wh,  const float* __restrict__ bh,
    const float* __restrict__ Wv,  const float* __restrict__ bv,
    const float* __restrict__ Wic, const float* __restrict__ bic,
    const float* __restrict__ Whc, const float* __restrict__ Wvc,
    const float* __restrict__ Wicc,
    float* __restrict__ out)
{
    float* sWh  = smem + SWH;
    float* sWv  = smem + SWV;
    float* sWic = smem + SWIC;

    const int tid  = threadIdx.x;
    const int wid  = tid >> 5;
    const int lane = tid & 31;
    const int r    = lane >> 2;      // row within warp group (0..7)
    const int fg   = lane & 3;       // feature slot (0..3)

    float* sBuf  = smem + SBUF + wid * BUF_F;
    int*   scode = reinterpret_cast<int*>(smem + SCODE) + wid * (RPW * NCAT);

    const int row0 = blockIdx.x * RPB + wid * RPW;   // first row of this warp
    const int row  = row0 + r;

    // ---- stage weights (block-wide, coalesced) ----
    {
        const float4* g = reinterpret_cast<const float4*>(Wh);
        float4* s = reinterpret_cast<float4*>(sWh);
        #pragma unroll
        for (int i = 0; i < 7; i++) s[tid + i * TPB] = __ldg(g + tid + i * TPB);
        g = reinterpret_cast<const float4*>(Wv);
        s = reinterpret_cast<float4*>(sWv);
        #pragma unroll
        for (int i = 0; i < 7; i++) s[tid + i * TPB] = __ldg(g + tid + i * TPB);
        if (tid < 224)
            reinterpret_cast<float4*>(sWic)[tid] =
                __ldg(reinterpret_cast<const float4*>(Wic) + tid);
    }

    // ---- warp-cooperative one-hot scan (fully coalesced, ~4 lines/instr) ----
    {
        const float4* gC = reinterpret_cast<const float4*>(Bcat);
        for (int rr = 0; rr < RPW; rr++) {
            const float4* base = gC + (size_t)(row0 + rr) * 200;
            #pragma unroll
            for (int t = 0; t < 7; t++) {
                int j = lane + t * 32;
                if (j < 200) {
                    float4 v = __ldg(base + j);
                    if (v.x > 0.5f || v.y > 0.5f || v.z > 0.5f || v.w > 0.5f) {
                        float vals[4] = {v.x, v.y, v.z, v.w};
                        #pragma unroll
                        for (int q = 0; q < 4; q++) {
                            if (vals[q] > 0.5f) {
                                int pos = j * 4 + q;
                                int f = pos / 100;
                                scode[rr * NCAT + f] = pos - f * 100;
                            }
                        }
                    }
                }
            }
        }
    }
    __syncthreads();   // weights staged + codes visible

    float hs[NCOMP], vs[NCOMP];
    #pragma unroll
    for (int c = 0; c < NCOMP; c++) { hs[c] = 0.0f; vs[c] = 0.0f; }
    float ic = 0.0f;

    // ---- categorical gathers: this lane handles cat features fg and fg+4 ----
    #pragma unroll
    for (int cf = 0; cf < 2; cf++) {
        const int f = fg + cf * 4;
        const int code = scode[r * NCAT + f];
        const int wrow = (f * NUNIQ + code) * NCOMP;
        const float4* wh = reinterpret_cast<const float4*>(Whc + wrow);
        const float4* wv = reinterpret_cast<const float4*>(Wvc + wrow);
        float4 a0 = __ldg(wh + 0), a1 = __ldg(wh + 1);
        float4 b0 = __ldg(wv + 0), b1 = __ldg(wv + 1);
        hs[0] += sp(a0.x); hs[1] += sp(a0.y); hs[2] += sp(a0.z); hs[3] += sp(a0.w);
        hs[4] += sp(a1.x); hs[5] += sp(a1.y); hs[6] += sp(a1.z); hs[7] += sp(a1.w);
        vs[0] += sp(b0.x); vs[1] += sp(b0.y); vs[2] += sp(b0.z); vs[3] += sp(b0.w);
        vs[4] += sp(b1.x); vs[5] += sp(b1.y); vs[6] += sp(b1.z); vs[7] += sp(b1.w);
        ic += __ldg(Wicc + f * NUNIQ + code);
    }

    // ---- main loop: per-warp B staging pipeline + smem-weight FMA core ----
    // staging geometry (fixed per lane): iter t covers rows 2t+(lane>>4), f4 m=lane&15
    const int rs_b = lane >> 4;
    const int m    = lane & 15;
    const float4* ldg0 = reinterpret_cast<const float4*>(B) + (size_t)(row0 + 0 + rs_b) * 224 + m;
    const float4* ldg1 = reinterpret_cast<const float4*>(B) + (size_t)(row0 + 2 + rs_b) * 224 + m;
    const float4* ldg2 = reinterpret_cast<const float4*>(B) + (size_t)(row0 + 4 + rs_b) * 224 + m;
    const float4* ldg3 = reinterpret_cast<const float4*>(B) + (size_t)(row0 + 6 + rs_b) * 224 + m;
    float* sts0 = sBuf + (0 + rs_b) * RPITCH + (m >> 2) * FPITCH + (m & 3) * 4;
    float* sts1 = sts0 + 2 * RPITCH;
    float* sts2 = sts0 + 4 * RPITCH;
    float* sts3 = sts0 + 6 * RPITCH;

    float4 nb0 = __ldg(ldg0), nb1 = __ldg(ldg1), nb2 = __ldg(ldg2), nb3 = __ldg(ldg3);
    ldg0 += 16; ldg1 += 16; ldg2 += 16; ldg3 += 16;

    const float* bbase = sBuf + r * RPITCH + fg * FPITCH;
    const float* whb   = sWh  + fg * NCOMP;   // advances 4*NCOMP per chunk
    const float* wvb   = sWv  + fg * NCOMP;
    const float* wicb  = sWic + fg;           // advances 4 per chunk

    for (int ch = 0; ch < NCHUNK; ch++) {
        __syncwarp();
        *reinterpret_cast<float4*>(sts0) = nb0;
        *reinterpret_cast<float4*>(sts1) = nb1;
        *reinterpret_cast<float4*>(sts2) = nb2;
        *reinterpret_cast<float4*>(sts3) = nb3;
        __syncwarp();
        if (ch + 1 < NCHUNK) {
            nb0 = __ldg(ldg0); nb1 = __ldg(ldg1);
            nb2 = __ldg(ldg2); nb3 = __ldg(ldg3);
            ldg0 += 16; ldg1 += 16; ldg2 += 16; ldg3 += 16;
        }

        // my feature = ch*4 + fg ; 16 basis values from conflict-free smem
        float4 b0 = *reinterpret_cast<const float4*>(bbase + 0);
        float4 b1 = *reinterpret_cast<const float4*>(bbase + 4);
        float4 b2 = *reinterpret_cast<const float4*>(bbase + 8);
        float4 b3 = *reinterpret_cast<const float4*>(bbase + 12);
        float bvv[NB] = {b0.x,b0.y,b0.z,b0.w, b1.x,b1.y,b1.z,b1.w,
                         b2.x,b2.y,b2.z,b2.w, b3.x,b3.y,b3.z,b3.w};

        float h[NCOMP], v[NCOMP];
        #pragma unroll
        for (int c = 0; c < NCOMP; c++) { h[c] = 0.0f; v[c] = 0.0f; }

        #pragma unroll
        for (int k = 0; k < NB; k++) {
            const float4* wh = reinterpret_cast<const float4*>(whb + k * (NCONT * NCOMP));
            const float4* wv = reinterpret_cast<const float4*>(wvb + k * (NCONT * NCOMP));
            float4 w0 = wh[0], w1 = wh[1];
            float4 u0 = wv[0], u1 = wv[1];
            const float wic = wicb[k * NCONT];
            const float bk = bvv[k];
            h[0] = fmaf(bk, w0.x, h[0]); h[1] = fmaf(bk, w0.y, h[1]);
            h[2] = fmaf(bk, w0.z, h[2]); h[3] = fmaf(bk, w0.w, h[3]);
            h[4] = fmaf(bk, w1.x, h[4]); h[5] = fmaf(bk, w1.y, h[5]);
            h[6] = fmaf(bk, w1.z, h[6]); h[7] = fmaf(bk, w1.w, h[7]);
            v[0] = fmaf(bk, u0.x, v[0]); v[1] = fmaf(bk, u0.y, v[1]);
            v[2] = fmaf(bk, u0.z, v[2]); v[3] = fmaf(bk, u0.w, v[3]);
            v[4] = fmaf(bk, u1.x, v[4]); v[5] = fmaf(bk, u1.y, v[5]);
            v[6] = fmaf(bk, u1.z, v[6]); v[7] = fmaf(bk, u1.w, v[7]);
            ic   = fmaf(bk, wic, ic);
        }
        #pragma unroll
        for (int c = 0; c < NCOMP; c++) { hs[c] += sp(h[c]); vs[c] += sp(v[c]); }

        whb  += FPC * NCOMP;
        wvb  += FPC * NCOMP;
        wicb += FPC;
    }

    // ---- reduce the 4 fg lanes of this row ----
    #pragma unroll
    for (int c = 0; c < NCOMP; c++) {
        hs[c] += __shfl_xor_sync(0xffffffffu, hs[c], 1);
        hs[c] += __shfl_xor_sync(0xffffffffu, hs[c], 2);
        vs[c] += __shfl_xor_sync(0xffffffffu, vs[c], 1);
        vs[c] += __shfl_xor_sync(0xffffffffu, vs[c], 2);
    }
    ic += __shfl_xor_sync(0xffffffffu, ic, 1);
    ic += __shfl_xor_sync(0xffffffffu, ic, 2);

    if (fg == 0) {
        #pragma unroll
        for (int c = 0; c < NCOMP; c++) {
            hs[c] += sp(__ldg(bh + c));
            vs[c] += sp(__ldg(bv + c));
        }
        ic += __ldg(bic);

        float2 o[NCOMP + 1];
        o[0] = make_float2(0.0f, ic);
        float cum = 0.0f, xc = ic;
        #pragma unroll
        for (int c = 0; c < NCOMP; c++) {
            cum += hs[c];
            xc  += (c & 1) ? -vs[c] : vs[c];
            o[c + 1] = make_float2(cum + SEPF * (float)(c + 1), xc);
        }
        o[NCOMP].x = fmaxf(o[NCOMP - 1].x + SEPF, T1F);

        float2* op = reinterpret_cast<float2*>(out + (size_t)row * 2 * (NCOMP + 1));
        #pragma unroll
        for (int j = 0; j < NCOMP + 1; j++) op[j] = o[j];
    }
}

extern "C" void kernel_launch(void* const* d_in, const int* in_sizes, int n_in,
                              void* d_out, int out_size)
{
    const float* B    = (const float*)d_in[0];
    const float* Bcat = (const float*)d_in[1];
    const float* Wh   = (const float*)d_in[2];
    const float* Whc  = (const float*)d_in[3];
    const float* bh   = (const float*)d_in[4];
    const float* Wv   = (const float*)d_in[5];
    const float* Wvc  = (const float*)d_in[6];
    const float* bv   = (const float*)d_in[7];
    const float* Wic  = (const float*)d_in[8];
    const float* Wicc = (const float*)d_in[9];
    const float* bic  = (const float*)d_in[10];
    float* out = (float*)d_out;

    const size_t smem = SMEM_F * sizeof(float);   // 83,456 B
    cudaFuncSetAttribute(k_main, cudaFuncAttributeMaxDynamicSharedMemorySize, (int)smem);

    k_main<<<BATCH / RPB, TPB, smem>>>(B, Bcat, Wh, bh, Wv, bv, Wic, bic,
                                       Whc, Wvc, Wicc, out);
}